// round 6
// baseline (speedup 1.0000x reference)
#include <cuda_runtime.h>
#include <cuda_fp16.h>
#include <cstdint>

// ---------------- problem dims ----------------
#define M_DIM 4096
#define K_DIM 4096
#define N_DIM 16384

// ================= scratch (no cudaMalloc allowed) =================
__device__ __align__(256) __half g_A[(size_t)M_DIM * K_DIM];   // 32 MB fp16 x
__device__ __align__(256) __half g_B[(size_t)N_DIM * K_DIM];   // 128 MB fp16 w

// ---------------- helpers ----------------
__device__ __forceinline__ uint32_t smem_u32(const void* p) {
    uint32_t a;
    asm("{ .reg .u64 t; cvta.to.shared.u64 t, %1; cvt.u32.u64 %0, t; }"
        : "=r"(a) : "l"(p));
    return a;
}

#define SWZ128(x) ((x) ^ (((x) >> 3) & 0x70))

#define CP_ASYNC16(dst, src) \
    asm volatile("cp.async.cg.shared.global [%0], [%1], 16;" \
                 :: "r"((uint32_t)(dst)), "l"(src) : "memory")
#define CP_COMMIT() asm volatile("cp.async.commit_group;" ::: "memory")
#define CP_WAIT(n)  asm volatile("cp.async.wait_group %0;" :: "n"(n) : "memory")

#define LDMX4(r0, r1, r2, r3, addr) \
    asm volatile("ldmatrix.sync.aligned.m8n8.x4.shared.b16 {%0,%1,%2,%3}, [%4];" \
                 : "=r"(r0), "=r"(r1), "=r"(r2), "=r"(r3) : "r"(addr))

// ================= prepass =================
// x: fp32 -> fp16
__global__ void __launch_bounds__(256) cvt_x_kernel(const float* __restrict__ x) {
    size_t gid = (size_t)blockIdx.x * blockDim.x + threadIdx.x;   // M*K/8
    const float4* s = (const float4*)x + gid * 2;
    float4 a = s[0], b = s[1];
    __half2 h0 = __floats2half2_rn(a.x, a.y);
    __half2 h1 = __floats2half2_rn(a.z, a.w);
    __half2 h2 = __floats2half2_rn(b.x, b.y);
    __half2 h3 = __floats2half2_rn(b.z, b.w);
    uint4 o;
    o.x = *(uint32_t*)&h0; o.y = *(uint32_t*)&h1;
    o.z = *(uint32_t*)&h2; o.w = *(uint32_t*)&h3;
    ((uint4*)g_A)[gid] = o;
}

// weight_q: delivered by the harness as INT32 (one sign-extended int8 per word).
__global__ void __launch_bounds__(256) cvt_w_kernel(const int* __restrict__ w) {
    size_t gid = (size_t)blockIdx.x * blockDim.x + threadIdx.x;   // N*K/16 threads
    const int4* s = (const int4*)w + gid * 4;
    uint4 o[2];
#pragma unroll
    for (int h = 0; h < 2; h++) {
        int4 v0 = s[h * 2], v1 = s[h * 2 + 1];
        __half2 p0 = __halves2half2(__float2half_rn((float)v0.x), __float2half_rn((float)v0.y));
        __half2 p1 = __halves2half2(__float2half_rn((float)v0.z), __float2half_rn((float)v0.w));
        __half2 p2 = __halves2half2(__float2half_rn((float)v1.x), __float2half_rn((float)v1.y));
        __half2 p3 = __halves2half2(__float2half_rn((float)v1.z), __float2half_rn((float)v1.w));
        o[h].x = *(uint32_t*)&p0; o[h].y = *(uint32_t*)&p1;
        o[h].z = *(uint32_t*)&p2; o[h].w = *(uint32_t*)&p3;
    }
    ((uint4*)g_B)[gid * 2 + 0] = o[0];
    ((uint4*)g_B)[gid * 2 + 1] = o[1];
}

// =====================================================================
// GEMM: cp.async + ldmatrix + mma.sync.m16n8k16, fragment double-buffered.
// CTA tile 128(M) x 256(N) x 64(K), 4-stage smem pipeline, 8 warps (2Mx4N),
// warp tile 64x64.
// =====================================================================
#define H_TM 128
#define H_TN 256
#define H_TK 64
#define H_KTILES (K_DIM / H_TK)
#define H_STAGES 4
#define HA_BYTES (H_TM * H_TK * 2)   // 16384
#define HB_BYTES (H_TN * H_TK * 2)   // 32768
#define H_STAGE (HA_BYTES + HB_BYTES)
#define H_SMEM (H_STAGES * H_STAGE)  // 196608

__global__ void __launch_bounds__(256, 1)
gemm_hmma(const float* __restrict__ scale, const float* __restrict__ bias,
          float* __restrict__ out) {
    extern __shared__ __align__(1024) char smem[];
    const uint32_t sb = smem_u32(smem);
    const int tid = threadIdx.x;
    const int lane = tid & 31;
    const int wid = tid >> 5;
    const int wm = wid & 1;           // 2 warps along M
    const int wn = wid >> 1;          // 4 warps along N

    const int nTN = N_DIM / H_TN;     // 64
    const int GROUPM = 8;
    const int npg = GROUPM * nTN;
    int pid = blockIdx.x;
    int grp = pid / npg;
    int inp = pid - grp * npg;
    int tm = grp * GROUPM + (inp % GROUPM);
    int tn = inp / GROUPM;

    const char* gA = (const char*)(g_A + (size_t)tm * H_TM * K_DIM);
    const char* gB = (const char*)(g_B + (size_t)tn * H_TN * K_DIM);

    auto load_stage = [&](int s, int kt) {
        uint32_t sa = sb + s * H_STAGE;
        uint32_t sB = sa + HA_BYTES;
        size_t kofs = (size_t)kt * 128;          // 64 halves = 128B
#pragma unroll
        for (int i = 0; i < 4; i++) {            // A: 128 rows x 8 chunks
            int c = tid + 256 * i;
            int row = c >> 3;
            int col = (c & 7) * 16;
            CP_ASYNC16(sa + SWZ128(row * 128 + col),
                       gA + (size_t)row * (K_DIM * 2) + kofs + col);
        }
#pragma unroll
        for (int i = 0; i < 8; i++) {            // B: 256 rows x 8 chunks
            int c = tid + 256 * i;
            int row = c >> 3;
            int col = (c & 7) * 16;
            CP_ASYNC16(sB + SWZ128(row * 128 + col),
                       gB + (size_t)row * (K_DIM * 2) + kofs + col);
        }
        CP_COMMIT();
    };

    float acc[4][8][4];
#pragma unroll
    for (int i = 0; i < 4; i++)
#pragma unroll
        for (int j = 0; j < 8; j++)
#pragma unroll
            for (int k = 0; k < 4; k++) acc[i][j][k] = 0.f;

    // ldmatrix lane-address components
    const int a_row = lane & 15;
    const int a_col = (lane >> 4) * 16;
    const int b_row = (lane & 7) + ((lane >> 4) << 3);
    const int b_col = ((lane >> 3) & 1) * 16;

    // fragment double buffers
    uint32_t afr[2][4][4], bfr[2][4][4];

    load_stage(0, 0);
    load_stage(1, 1);
    load_stage(2, 2);

    for (int kt = 0; kt < H_KTILES; kt++) {
        if (kt + 1 >= H_KTILES)      { CP_WAIT(0); }
        else if (kt + 2 >= H_KTILES) { CP_WAIT(1); }
        else                         { CP_WAIT(2); }
        __syncthreads();
        if (kt + 3 < H_KTILES) load_stage((kt + 3) & 3, kt + 3);

        uint32_t sa = sb + (kt & 3) * H_STAGE;
        uint32_t sB = sa + HA_BYTES;

        // prime fragments for ks = 0
#pragma unroll
        for (int mt = 0; mt < 4; mt++) {
            int row = wm * 64 + mt * 16 + a_row;
            LDMX4(afr[0][mt][0], afr[0][mt][1], afr[0][mt][2], afr[0][mt][3],
                  sa + SWZ128(row * 128 + a_col));
        }
#pragma unroll
        for (int nt2 = 0; nt2 < 4; nt2++) {
            int row = wn * 64 + nt2 * 16 + b_row;
            LDMX4(bfr[0][nt2][0], bfr[0][nt2][1], bfr[0][nt2][2], bfr[0][nt2][3],
                  sB + SWZ128(row * 128 + b_col));
        }

#pragma unroll
        for (int ks = 0; ks < 4; ks++) {
            const int cur = ks & 1;
            const int nxt = cur ^ 1;
            if (ks < 3) {
                int colb = (ks + 1) * 32;
#pragma unroll
                for (int mt = 0; mt < 4; mt++) {
                    int row = wm * 64 + mt * 16 + a_row;
                    LDMX4(afr[nxt][mt][0], afr[nxt][mt][1], afr[nxt][mt][2], afr[nxt][mt][3],
                          sa + SWZ128(row * 128 + colb + a_col));
                }
#pragma unroll
                for (int nt2 = 0; nt2 < 4; nt2++) {
                    int row = wn * 64 + nt2 * 16 + b_row;
                    LDMX4(bfr[nxt][nt2][0], bfr[nxt][nt2][1], bfr[nxt][nt2][2], bfr[nxt][nt2][3],
                          sB + SWZ128(row * 128 + colb + b_col));
                }
            }
#pragma unroll
            for (int mt = 0; mt < 4; mt++) {
#pragma unroll
                for (int nt = 0; nt < 8; nt++) {
                    uint32_t b0 = (nt & 1) ? bfr[cur][nt >> 1][2] : bfr[cur][nt >> 1][0];
                    uint32_t b1 = (nt & 1) ? bfr[cur][nt >> 1][3] : bfr[cur][nt >> 1][1];
                    asm volatile(
                        "mma.sync.aligned.m16n8k16.row.col.f32.f16.f16.f32 "
                        "{%0,%1,%2,%3}, {%4,%5,%6,%7}, {%8,%9}, {%0,%1,%2,%3};"
                        : "+f"(acc[mt][nt][0]), "+f"(acc[mt][nt][1]),
                          "+f"(acc[mt][nt][2]), "+f"(acc[mt][nt][3])
                        : "r"(afr[cur][mt][0]), "r"(afr[cur][mt][1]),
                          "r"(afr[cur][mt][2]), "r"(afr[cur][mt][3]),
                          "r"(b0), "r"(b1));
                }
            }
        }
    }

    // ---- epilogue: fuse per-channel scale + bias ----
    float2 sc2[8], bi2[8];
#pragma unroll
    for (int nt = 0; nt < 8; nt++) {
        int cn = tn * H_TN + wn * 64 + nt * 8 + 2 * (lane & 3);
        sc2[nt] = *(const float2*)(scale + cn);
        bi2[nt] = *(const float2*)(bias + cn);
    }
#pragma unroll
    for (int mt = 0; mt < 4; mt++) {
        int r0 = tm * H_TM + wm * 64 + mt * 16 + (lane >> 2);
        int r1 = r0 + 8;
#pragma unroll
        for (int nt = 0; nt < 8; nt++) {
            int cn = tn * H_TN + wn * 64 + nt * 8 + 2 * (lane & 3);
            float2 o0, o1;
            o0.x = acc[mt][nt][0] * sc2[nt].x + bi2[nt].x;
            o0.y = acc[mt][nt][1] * sc2[nt].y + bi2[nt].y;
            o1.x = acc[mt][nt][2] * sc2[nt].x + bi2[nt].x;
            o1.y = acc[mt][nt][3] * sc2[nt].y + bi2[nt].y;
            *(float2*)(out + (size_t)r0 * N_DIM + cn) = o0;
            *(float2*)(out + (size_t)r1 * N_DIM + cn) = o1;
        }
    }
}

// ---------------- launch ----------------
extern "C" void kernel_launch(void* const* d_in, const int* in_sizes, int n_in,
                              void* d_out, int out_size) {
    const float* x     = (const float*)d_in[0];
    const int*   w     = (const int*)d_in[1];   // int8 values shipped as int32
    const float* scale = (const float*)d_in[2];
    const float* bias  = (const float*)d_in[3];
    float*       out   = (float*)d_out;

    cudaFuncSetAttribute(gemm_hmma,
                         cudaFuncAttributeMaxDynamicSharedMemorySize, H_SMEM);

    cvt_x_kernel<<<(int)((size_t)M_DIM * K_DIM / 8 / 256), 256>>>(x);
    cvt_w_kernel<<<(int)((size_t)N_DIM * K_DIM / 16 / 256), 256>>>(w);
    gemm_hmma<<<(M_DIM / H_TM) * (N_DIM / H_TN), 256, H_SMEM>>>(scale, bias, out);
}

// round 7
// speedup vs baseline: 1.0856x; 1.0856x over previous
#include <cuda_runtime.h>
#include <cuda_fp16.h>
#include <cstdint>

// ---------------- problem dims ----------------
#define M_DIM 4096
#define K_DIM 4096
#define N_DIM 16384

// ================= scratch (no cudaMalloc allowed) =================
__device__ __align__(256) __half g_A[(size_t)M_DIM * K_DIM];   // 32 MB fp16 x
__device__ __align__(256) __half g_B[(size_t)N_DIM * K_DIM];   // 128 MB fp16 w

// ---------------- helpers ----------------
__device__ __forceinline__ uint32_t smem_u32(const void* p) {
    uint32_t a;
    asm("{ .reg .u64 t; cvta.to.shared.u64 t, %1; cvt.u32.u64 %0, t; }"
        : "=r"(a) : "l"(p));
    return a;
}

#define SWZ128(x) ((x) ^ (((x) >> 3) & 0x70))

#define CP_ASYNC16(dst, src) \
    asm volatile("cp.async.cg.shared.global [%0], [%1], 16;" \
                 :: "r"((uint32_t)(dst)), "l"(src) : "memory")
#define CP_COMMIT() asm volatile("cp.async.commit_group;" ::: "memory")
#define CP_WAIT(n)  asm volatile("cp.async.wait_group %0;" :: "n"(n) : "memory")

#define LDMX4(r0, r1, r2, r3, addr) \
    asm volatile("ldmatrix.sync.aligned.m8n8.x4.shared.b16 {%0,%1,%2,%3}, [%4];" \
                 : "=r"(r0), "=r"(r1), "=r"(r2), "=r"(r3) : "r"(addr))

// named barrier scoped to one 128-thread group
#define GROUP_BAR(id) \
    asm volatile("bar.sync %0, 128;" :: "r"(id) : "memory")

// ================= fused prepass =================
// blocks [0, XB): x fp32 -> fp16 (8 elems/thread)
// blocks [XB, XB+WB): weight int32 (sign-extended int8) -> fp16 (16 elems/thread)
#define XB ((int)((size_t)M_DIM * K_DIM / 8 / 256))    // 8192
#define WB ((int)((size_t)N_DIM * K_DIM / 16 / 256))   // 16384

__global__ void __launch_bounds__(256) cvt_kernel(const float* __restrict__ x,
                                                  const int* __restrict__ w) {
    if (blockIdx.x < XB) {
        size_t gid = (size_t)blockIdx.x * 256 + threadIdx.x;
        const float4* s = (const float4*)x + gid * 2;
        float4 a = s[0], b = s[1];
        __half2 h0 = __floats2half2_rn(a.x, a.y);
        __half2 h1 = __floats2half2_rn(a.z, a.w);
        __half2 h2 = __floats2half2_rn(b.x, b.y);
        __half2 h3 = __floats2half2_rn(b.z, b.w);
        uint4 o;
        o.x = *(uint32_t*)&h0; o.y = *(uint32_t*)&h1;
        o.z = *(uint32_t*)&h2; o.w = *(uint32_t*)&h3;
        ((uint4*)g_A)[gid] = o;
    } else {
        size_t gid = (size_t)(blockIdx.x - XB) * 256 + threadIdx.x;
        const int4* s = (const int4*)w + gid * 4;
        uint4 o[2];
#pragma unroll
        for (int h = 0; h < 2; h++) {
            int4 v0 = s[h * 2], v1 = s[h * 2 + 1];
            __half2 p0 = __halves2half2(__float2half_rn((float)v0.x), __float2half_rn((float)v0.y));
            __half2 p1 = __halves2half2(__float2half_rn((float)v0.z), __float2half_rn((float)v0.w));
            __half2 p2 = __halves2half2(__float2half_rn((float)v1.x), __float2half_rn((float)v1.y));
            __half2 p3 = __halves2half2(__float2half_rn((float)v1.z), __float2half_rn((float)v1.w));
            o[h].x = *(uint32_t*)&p0; o[h].y = *(uint32_t*)&p1;
            o[h].z = *(uint32_t*)&p2; o[h].w = *(uint32_t*)&p3;
        }
        ((uint4*)g_B)[gid * 2 + 0] = o[0];
        ((uint4*)g_B)[gid * 2 + 1] = o[1];
    }
}

// =====================================================================
// GEMM: CTA = 128(M) x 256(N); TWO independent 128-thread groups, each
// computing a 128x128 N-half with its OWN 3-stage cp.async pipeline and
// named barrier. Groups never inter-sync -> bubbles of one group are
// covered by the other group's HMMAs on the same SMSPs.
// Per group: 4 warps (2M x 2N), warp tile 64x64, mma.sync.m16n8k16.
// =====================================================================
#define G_TK 64
#define G_KTILES (K_DIM / G_TK)      // 64
#define G_NSTAGES 3
#define GA_BYTES (128 * G_TK * 2)    // 16384
#define GB_BYTES (128 * G_TK * 2)    // 16384
#define G_STAGE (GA_BYTES + GB_BYTES)          // 32768
#define G_SMEM_PER (G_NSTAGES * G_STAGE)       // 98304
#define H_SMEM (2 * G_SMEM_PER)                // 196608

__global__ void __launch_bounds__(256, 1)
gemm_hmma(const float* __restrict__ scale, const float* __restrict__ bias,
          float* __restrict__ out) {
    extern __shared__ __align__(1024) char smem[];
    const int tid = threadIdx.x;
    const int lane = tid & 31;
    const int wid = tid >> 5;
    const int g = wid >> 2;            // group 0 / 1
    const int wg = wid & 3;            // warp within group
    const int wm = wg & 1;             // 2 warps along M
    const int wn = wg >> 1;            // 2 warps along N
    const int tg = tid & 127;          // thread within group
    const uint32_t sg = smem_u32(smem) + g * G_SMEM_PER;

    // tile rasterization with GROUP_M=8 supergroups (L2 reuse)
    const int nTN = N_DIM / 256;       // 64
    const int GROUPM = 8;
    const int npg = GROUPM * nTN;
    int pid = blockIdx.x;
    int grp = pid / npg;
    int inp = pid - grp * npg;
    int tm = grp * GROUPM + (inp % GROUPM);
    int tn = inp / GROUPM;

    const char* gA = (const char*)(g_A + (size_t)tm * 128 * K_DIM);
    const char* gB = (const char*)(g_B + ((size_t)tn * 256 + g * 128) * K_DIM);

    // per-group stage fill: A 128x64 fp16 + B 128x64 fp16, 16B chunks,
    // 1024+1024 chunks over 128 threads -> 8+8 per thread.
    auto load_stage = [&](int s, int kt) {
        uint32_t sa = sg + s * G_STAGE;
        uint32_t sB = sa + GA_BYTES;
        size_t kofs = (size_t)kt * 128;          // 64 halves = 128B
#pragma unroll
        for (int i = 0; i < 8; i++) {
            int c = tg + 128 * i;
            int row = c >> 3;
            int col = (c & 7) * 16;
            CP_ASYNC16(sa + SWZ128(row * 128 + col),
                       gA + (size_t)row * (K_DIM * 2) + kofs + col);
        }
#pragma unroll
        for (int i = 0; i < 8; i++) {
            int c = tg + 128 * i;
            int row = c >> 3;
            int col = (c & 7) * 16;
            CP_ASYNC16(sB + SWZ128(row * 128 + col),
                       gB + (size_t)row * (K_DIM * 2) + kofs + col);
        }
        CP_COMMIT();
    };

    float acc[4][8][4];
#pragma unroll
    for (int i = 0; i < 4; i++)
#pragma unroll
        for (int j = 0; j < 8; j++)
#pragma unroll
            for (int k = 0; k < 4; k++) acc[i][j][k] = 0.f;

    // ldmatrix lane-address components
    const int a_row = lane & 15;
    const int a_col = (lane >> 4) * 16;
    const int b_row = (lane & 7) + ((lane >> 4) << 3);
    const int b_col = ((lane >> 3) & 1) * 16;

    load_stage(0, 0);
    load_stage(1, 1);

    for (int kt = 0; kt < G_KTILES; kt++) {
        if (kt + 1 >= G_KTILES) { CP_WAIT(0); }
        else                    { CP_WAIT(1); }
        GROUP_BAR(1 + g);
        if (kt + 2 < G_KTILES) load_stage((kt + 2) % G_NSTAGES, kt + 2);

        uint32_t sa = sg + (kt % G_NSTAGES) * G_STAGE;
        uint32_t sB = sa + GA_BYTES;

#pragma unroll
        for (int ks = 0; ks < 4; ks++) {
            int colb = ks * 32;
            uint32_t afr[4][4];
#pragma unroll
            for (int mt = 0; mt < 4; mt++) {
                int row = wm * 64 + mt * 16 + a_row;
                LDMX4(afr[mt][0], afr[mt][1], afr[mt][2], afr[mt][3],
                      sa + SWZ128(row * 128 + colb + a_col));
            }
            uint32_t bfr[4][4];
#pragma unroll
            for (int nt2 = 0; nt2 < 4; nt2++) {
                int row = wn * 64 + nt2 * 16 + b_row;
                LDMX4(bfr[nt2][0], bfr[nt2][1], bfr[nt2][2], bfr[nt2][3],
                      sB + SWZ128(row * 128 + colb + b_col));
            }
#pragma unroll
            for (int mt = 0; mt < 4; mt++) {
#pragma unroll
                for (int nt = 0; nt < 8; nt++) {
                    uint32_t b0 = (nt & 1) ? bfr[nt >> 1][2] : bfr[nt >> 1][0];
                    uint32_t b1 = (nt & 1) ? bfr[nt >> 1][3] : bfr[nt >> 1][1];
                    asm volatile(
                        "mma.sync.aligned.m16n8k16.row.col.f32.f16.f16.f32 "
                        "{%0,%1,%2,%3}, {%4,%5,%6,%7}, {%8,%9}, {%0,%1,%2,%3};"
                        : "+f"(acc[mt][nt][0]), "+f"(acc[mt][nt][1]),
                          "+f"(acc[mt][nt][2]), "+f"(acc[mt][nt][3])
                        : "r"(afr[mt][0]), "r"(afr[mt][1]),
                          "r"(afr[mt][2]), "r"(afr[mt][3]),
                          "r"(b0), "r"(b1));
                }
            }
        }
    }

    // ---- epilogue: fuse per-channel scale + bias ----
    const int ncol0 = tn * 256 + g * 128 + wn * 64;
    float2 sc2[8], bi2[8];
#pragma unroll
    for (int nt = 0; nt < 8; nt++) {
        int cn = ncol0 + nt * 8 + 2 * (lane & 3);
        sc2[nt] = *(const float2*)(scale + cn);
        bi2[nt] = *(const float2*)(bias + cn);
    }
#pragma unroll
    for (int mt = 0; mt < 4; mt++) {
        int r0 = tm * 128 + wm * 64 + mt * 16 + (lane >> 2);
        int r1 = r0 + 8;
#pragma unroll
        for (int nt = 0; nt < 8; nt++) {
            int cn = ncol0 + nt * 8 + 2 * (lane & 3);
            float2 o0, o1;
            o0.x = acc[mt][nt][0] * sc2[nt].x + bi2[nt].x;
            o0.y = acc[mt][nt][1] * sc2[nt].y + bi2[nt].y;
            o1.x = acc[mt][nt][2] * sc2[nt].x + bi2[nt].x;
            o1.y = acc[mt][nt][3] * sc2[nt].y + bi2[nt].y;
            *(float2*)(out + (size_t)r0 * N_DIM + cn) = o0;
            *(float2*)(out + (size_t)r1 * N_DIM + cn) = o1;
        }
    }
}

// ---------------- launch ----------------
extern "C" void kernel_launch(void* const* d_in, const int* in_sizes, int n_in,
                              void* d_out, int out_size) {
    const float* x     = (const float*)d_in[0];
    const int*   w     = (const int*)d_in[1];   // int8 values shipped as int32
    const float* scale = (const float*)d_in[2];
    const float* bias  = (const float*)d_in[3];
    float*       out   = (float*)d_out;

    cudaFuncSetAttribute(gemm_hmma,
                         cudaFuncAttributeMaxDynamicSharedMemorySize, H_SMEM);

    cvt_kernel<<<XB + WB, 256>>>(x, w);
    gemm_hmma<<<(M_DIM / 128) * (N_DIM / 256), 256, H_SMEM>>>(scale, bias, out);
}

// round 8
// speedup vs baseline: 1.1023x; 1.0154x over previous
#include <cuda_runtime.h>
#include <cuda_fp16.h>
#include <cstdint>

// ---------------- problem dims ----------------
#define M_DIM 4096
#define K_DIM 4096
#define N_DIM 16384

// ================= scratch (no cudaMalloc allowed) =================
__device__ __align__(256) __half g_A[(size_t)M_DIM * K_DIM];   // 32 MB fp16 x
__device__ __align__(256) __half g_B[(size_t)N_DIM * K_DIM];   // 128 MB fp16 w

// ---------------- helpers ----------------
__device__ __forceinline__ uint32_t smem_u32(const void* p) {
    uint32_t a;
    asm("{ .reg .u64 t; cvta.to.shared.u64 t, %1; cvt.u32.u64 %0, t; }"
        : "=r"(a) : "l"(p));
    return a;
}

#define SWZ128(x) ((x) ^ (((x) >> 3) & 0x70))

#define CP_ASYNC16(dst, src) \
    asm volatile("cp.async.cg.shared.global [%0], [%1], 16;" \
                 :: "r"((uint32_t)(dst)), "l"(src) : "memory")
#define CP_COMMIT() asm volatile("cp.async.commit_group;" ::: "memory")
#define CP_WAIT(n)  asm volatile("cp.async.wait_group %0;" :: "n"(n) : "memory")

#define LDMX4(r0, r1, r2, r3, addr) \
    asm volatile("ldmatrix.sync.aligned.m8n8.x4.shared.b16 {%0,%1,%2,%3}, [%4];" \
                 : "=r"(r0), "=r"(r1), "=r"(r2), "=r"(r3) : "r"(addr))

#define GROUP_BAR(id) \
    asm volatile("bar.sync %0, 128;" :: "r"(id) : "memory")

// streaming 16B store (evict-first: don't pollute L2)
__device__ __forceinline__ void stcs16(void* p, uint4 v) {
    asm volatile("st.global.cs.v4.b32 [%0], {%1,%2,%3,%4};"
                 :: "l"(p), "r"(v.x), "r"(v.y), "r"(v.z), "r"(v.w) : "memory");
}
__device__ __forceinline__ void stcs8(void* p, float2 v) {
    asm volatile("st.global.cs.v2.f32 [%0], {%1,%2};"
                 :: "l"(p), "f"(v.x), "f"(v.y) : "memory");
}

// ================= fused prepass =================
#define XB ((int)((size_t)M_DIM * K_DIM / 8 / 256))    // 8192
#define WB ((int)((size_t)N_DIM * K_DIM / 16 / 256))   // 16384

__global__ void __launch_bounds__(256) cvt_kernel(const float* __restrict__ x,
                                                  const int* __restrict__ w) {
    if (blockIdx.x < XB) {
        size_t gid = (size_t)blockIdx.x * 256 + threadIdx.x;
        const float4* s = (const float4*)x + gid * 2;
        float4 a = s[0], b = s[1];
        __half2 h0 = __floats2half2_rn(a.x, a.y);
        __half2 h1 = __floats2half2_rn(a.z, a.w);
        __half2 h2 = __floats2half2_rn(b.x, b.y);
        __half2 h3 = __floats2half2_rn(b.z, b.w);
        uint4 o;
        o.x = *(uint32_t*)&h0; o.y = *(uint32_t*)&h1;
        o.z = *(uint32_t*)&h2; o.w = *(uint32_t*)&h3;
        stcs16((uint4*)g_A + gid, o);
    } else {
        size_t gid = (size_t)(blockIdx.x - XB) * 256 + threadIdx.x;
        const int4* s = (const int4*)w + gid * 4;
#pragma unroll
        for (int h = 0; h < 2; h++) {
            int4 v0 = s[h * 2], v1 = s[h * 2 + 1];
            __half2 p0 = __halves2half2(__float2half_rn((float)v0.x), __float2half_rn((float)v0.y));
            __half2 p1 = __halves2half2(__float2half_rn((float)v0.z), __float2half_rn((float)v0.w));
            __half2 p2 = __halves2half2(__float2half_rn((float)v1.x), __float2half_rn((float)v1.y));
            __half2 p3 = __halves2half2(__float2half_rn((float)v1.z), __float2half_rn((float)v1.w));
            uint4 o;
            o.x = *(uint32_t*)&p0; o.y = *(uint32_t*)&p1;
            o.z = *(uint32_t*)&p2; o.w = *(uint32_t*)&p3;
            stcs16((uint4*)g_B + gid * 2 + h, o);
        }
    }
}

// =====================================================================
// GEMM: CTA = 128(M) x 256(N); two independent 128-thread groups, each a
// 128x128 N-half with its own 3-stage cp.async ring + named barrier.
// Per group: 4 warps (2M x 2N), warp tile 64x64, mma.sync.m16n8k16.
// =====================================================================
#define G_TK 64
#define G_KTILES (K_DIM / G_TK)      // 64
#define G_NSTAGES 3
#define GA_BYTES (128 * G_TK * 2)    // 16384
#define GB_BYTES (128 * G_TK * 2)    // 16384
#define G_STAGE (GA_BYTES + GB_BYTES)          // 32768
#define G_SMEM_PER (G_NSTAGES * G_STAGE)       // 98304
#define H_SMEM (2 * G_SMEM_PER)                // 196608

__global__ void __launch_bounds__(256, 1)
gemm_hmma(const float* __restrict__ scale, const float* __restrict__ bias,
          float* __restrict__ out) {
    extern __shared__ __align__(1024) char smem[];
    const int tid = threadIdx.x;
    const int lane = tid & 31;
    const int wid = tid >> 5;
    const int g = wid >> 2;            // group 0 / 1
    const int wg = wid & 3;
    const int wm = wg & 1;             // 2 warps along M
    const int wn = wg >> 1;            // 2 warps along N
    const int tg = tid & 127;
    const uint32_t sg = smem_u32(smem) + g * G_SMEM_PER;

    // tile rasterization: 8 consecutive CTAs share one tn (B tile in L2)
    const int nTN = N_DIM / 256;       // 64
    const int GROUPM = 8;
    const int npg = GROUPM * nTN;
    int pid = blockIdx.x;
    int grp = pid / npg;
    int inp = pid - grp * npg;
    int tm = grp * GROUPM + (inp % GROUPM);
    int tn = inp / GROUPM;

    const char* gA = (const char*)(g_A + (size_t)tm * 128 * K_DIM);
    const char* gB = (const char*)(g_B + ((size_t)tn * 256 + g * 128) * K_DIM);

    auto load_stage = [&](int s, int kt) {
        uint32_t sa = sg + s * G_STAGE;
        uint32_t sB = sa + GA_BYTES;
        size_t kofs = (size_t)kt * 128;
#pragma unroll
        for (int i = 0; i < 8; i++) {
            int c = tg + 128 * i;
            int row = c >> 3;
            int col = (c & 7) * 16;
            CP_ASYNC16(sa + SWZ128(row * 128 + col),
                       gA + (size_t)row * (K_DIM * 2) + kofs + col);
        }
#pragma unroll
        for (int i = 0; i < 8; i++) {
            int c = tg + 128 * i;
            int row = c >> 3;
            int col = (c & 7) * 16;
            CP_ASYNC16(sB + SWZ128(row * 128 + col),
                       gB + (size_t)row * (K_DIM * 2) + kofs + col);
        }
        CP_COMMIT();
    };

    float acc[4][8][4];
#pragma unroll
    for (int i = 0; i < 4; i++)
#pragma unroll
        for (int j = 0; j < 8; j++)
#pragma unroll
            for (int k = 0; k < 4; k++) acc[i][j][k] = 0.f;

    const int a_row = lane & 15;
    const int a_col = (lane >> 4) * 16;
    const int b_row = (lane & 7) + ((lane >> 4) << 3);
    const int b_col = ((lane >> 3) & 1) * 16;

    // one ks-step: LDSM (interleaved: a0 then b0..b3 then a1..a3) + 32 MMA
    auto do_ks = [&](uint32_t sa, uint32_t sB, int ks) {
        int colb = ks * 32;
        uint32_t afr[4][4], bfr[4][4];
        {
            int row = wm * 64 + a_row;
            LDMX4(afr[0][0], afr[0][1], afr[0][2], afr[0][3],
                  sa + SWZ128(row * 128 + colb + a_col));
        }
#pragma unroll
        for (int nt2 = 0; nt2 < 4; nt2++) {
            int row = wn * 64 + nt2 * 16 + b_row;
            LDMX4(bfr[nt2][0], bfr[nt2][1], bfr[nt2][2], bfr[nt2][3],
                  sB + SWZ128(row * 128 + colb + b_col));
        }
#pragma unroll
        for (int mt = 1; mt < 4; mt++) {
            int row = wm * 64 + mt * 16 + a_row;
            LDMX4(afr[mt][0], afr[mt][1], afr[mt][2], afr[mt][3],
                  sa + SWZ128(row * 128 + colb + a_col));
        }
#pragma unroll
        for (int mt = 0; mt < 4; mt++) {
#pragma unroll
            for (int nt = 0; nt < 8; nt++) {
                uint32_t b0 = (nt & 1) ? bfr[nt >> 1][2] : bfr[nt >> 1][0];
                uint32_t b1 = (nt & 1) ? bfr[nt >> 1][3] : bfr[nt >> 1][1];
                asm volatile(
                    "mma.sync.aligned.m16n8k16.row.col.f32.f16.f16.f32 "
                    "{%0,%1,%2,%3}, {%4,%5,%6,%7}, {%8,%9}, {%0,%1,%2,%3};"
                    : "+f"(acc[mt][nt][0]), "+f"(acc[mt][nt][1]),
                      "+f"(acc[mt][nt][2]), "+f"(acc[mt][nt][3])
                    : "r"(afr[mt][0]), "r"(afr[mt][1]),
                      "r"(afr[mt][2]), "r"(afr[mt][3]),
                      "r"(b0), "r"(b1));
            }
        }
    };

    load_stage(0, 0);
    load_stage(1, 1);

    int s_cur = 0, s_pre = 2;          // stage being computed / stage to prefetch into
    for (int kt = 0; kt < G_KTILES; kt++) {
        if (kt + 1 >= G_KTILES) { CP_WAIT(0); }
        else                    { CP_WAIT(1); }
        GROUP_BAR(1 + g);

        uint32_t sa = sg + s_cur * G_STAGE;
        uint32_t sB = sa + GA_BYTES;

        // critical LDSMs first, THEN the cp.async burst for kt+2
        do_ks(sa, sB, 0);
        if (kt + 2 < G_KTILES) load_stage(s_pre, kt + 2);
        do_ks(sa, sB, 1);
        do_ks(sa, sB, 2);
        do_ks(sa, sB, 3);

        if (++s_cur == G_NSTAGES) s_cur = 0;
        if (++s_pre == G_NSTAGES) s_pre = 0;
    }

    // ---- epilogue: fuse per-channel scale + bias, streaming stores ----
    const int ncol0 = tn * 256 + g * 128 + wn * 64;
    float2 sc2[8], bi2[8];
#pragma unroll
    for (int nt = 0; nt < 8; nt++) {
        int cn = ncol0 + nt * 8 + 2 * (lane & 3);
        sc2[nt] = *(const float2*)(scale + cn);
        bi2[nt] = *(const float2*)(bias + cn);
    }
#pragma unroll
    for (int mt = 0; mt < 4; mt++) {
        int r0 = tm * 128 + wm * 64 + mt * 16 + (lane >> 2);
        int r1 = r0 + 8;
#pragma unroll
        for (int nt = 0; nt < 8; nt++) {
            int cn = ncol0 + nt * 8 + 2 * (lane & 3);
            float2 o0, o1;
            o0.x = acc[mt][nt][0] * sc2[nt].x + bi2[nt].x;
            o0.y = acc[mt][nt][1] * sc2[nt].y + bi2[nt].y;
            o1.x = acc[mt][nt][2] * sc2[nt].x + bi2[nt].x;
            o1.y = acc[mt][nt][3] * sc2[nt].y + bi2[nt].y;
            stcs8(out + (size_t)r0 * N_DIM + cn, o0);
            stcs8(out + (size_t)r1 * N_DIM + cn, o1);
        }
    }
}

// ---------------- launch ----------------
extern "C" void kernel_launch(void* const* d_in, const int* in_sizes, int n_in,
                              void* d_out, int out_size) {
    const float* x     = (const float*)d_in[0];
    const int*   w     = (const int*)d_in[1];   // int8 values shipped as int32
    const float* scale = (const float*)d_in[2];
    const float* bias  = (const float*)d_in[3];
    float*       out   = (float*)d_out;

    cudaFuncSetAttribute(gemm_hmma,
                         cudaFuncAttributeMaxDynamicSharedMemorySize, H_SMEM);

    cvt_kernel<<<XB + WB, 256>>>(x, w);
    gemm_hmma<<<(M_DIM / 128) * (N_DIM / 256), 256, H_SMEM>>>(scale, bias, out);
}

// round 10
// speedup vs baseline: 1.1825x; 1.0728x over previous
#include <cuda_runtime.h>
#include <cuda_fp16.h>
#include <cstdint>

// ---------------- problem dims ----------------
#define M_DIM 4096
#define K_DIM 4096
#define N_DIM 16384

// ================= scratch (no cudaMalloc allowed) =================
__device__ __align__(256) __half g_A[(size_t)M_DIM * K_DIM];   // 32 MB fp16 x
__device__ __align__(256) __half g_B[(size_t)N_DIM * K_DIM];   // 128 MB fp16 w

// ---------------- helpers ----------------
__device__ __forceinline__ uint32_t smem_u32(const void* p) {
    uint32_t a;
    asm("{ .reg .u64 t; cvta.to.shared.u64 t, %1; cvt.u32.u64 %0, t; }"
        : "=r"(a) : "l"(p));
    return a;
}

#define SWZ128(x) ((x) ^ (((x) >> 3) & 0x70))

#define CP_ASYNC16(dst, src) \
    asm volatile("cp.async.cg.shared.global [%0], [%1], 16;" \
                 :: "r"((uint32_t)(dst)), "l"(src) : "memory")
#define CP_COMMIT() asm volatile("cp.async.commit_group;" ::: "memory")
#define CP_WAIT(n)  asm volatile("cp.async.wait_group %0;" :: "n"(n) : "memory")

#define LDMX4(r0, r1, r2, r3, addr) \
    asm volatile("ldmatrix.sync.aligned.m8n8.x4.shared.b16 {%0,%1,%2,%3}, [%4];" \
                 : "=r"(r0), "=r"(r1), "=r"(r2), "=r"(r3) : "r"(addr))

#define GROUP_BAR(id) \
    asm volatile("bar.sync %0, 128;" :: "r"(id) : "memory")

__device__ __forceinline__ void stcs16(void* p, uint4 v) {
    asm volatile("st.global.cs.v4.b32 [%0], {%1,%2,%3,%4};"
                 :: "l"(p), "r"(v.x), "r"(v.y), "r"(v.z), "r"(v.w) : "memory");
}
__device__ __forceinline__ void stcs8(void* p, float2 v) {
    asm volatile("st.global.cs.v2.f32 [%0], {%1,%2};"
                 :: "l"(p), "f"(v.x), "f"(v.y) : "memory");
}

// ================= fused prepass =================
#define XB ((int)((size_t)M_DIM * K_DIM / 8 / 256))    // 8192
#define WB ((int)((size_t)N_DIM * K_DIM / 16 / 256))   // 16384

__global__ void __launch_bounds__(256) cvt_kernel(const float* __restrict__ x,
                                                  const int* __restrict__ w) {
    if (blockIdx.x < XB) {
        size_t gid = (size_t)blockIdx.x * 256 + threadIdx.x;
        const float4* s = (const float4*)x + gid * 2;
        float4 a = s[0], b = s[1];
        __half2 h0 = __floats2half2_rn(a.x, a.y);
        __half2 h1 = __floats2half2_rn(a.z, a.w);
        __half2 h2 = __floats2half2_rn(b.x, b.y);
        __half2 h3 = __floats2half2_rn(b.z, b.w);
        uint4 o;
        o.x = *(uint32_t*)&h0; o.y = *(uint32_t*)&h1;
        o.z = *(uint32_t*)&h2; o.w = *(uint32_t*)&h3;
        ((uint4*)g_A)[gid] = o;   // x-scratch: keep L2-resident (reused 64x)
    } else {
        size_t gid = (size_t)(blockIdx.x - XB) * 256 + threadIdx.x;
        const int4* s = (const int4*)w + gid * 4;
#pragma unroll
        for (int h = 0; h < 2; h++) {
            int4 v0 = s[h * 2], v1 = s[h * 2 + 1];
            __half2 p0 = __halves2half2(__float2half_rn((float)v0.x), __float2half_rn((float)v0.y));
            __half2 p1 = __halves2half2(__float2half_rn((float)v0.z), __float2half_rn((float)v0.w));
            __half2 p2 = __halves2half2(__float2half_rn((float)v1.x), __float2half_rn((float)v1.y));
            __half2 p3 = __halves2half2(__float2half_rn((float)v1.z), __float2half_rn((float)v1.w));
            uint4 o;
            o.x = *(uint32_t*)&p0; o.y = *(uint32_t*)&p1;
            o.z = *(uint32_t*)&p2; o.w = *(uint32_t*)&p3;
            stcs16((uint4*)g_B + gid * 2 + h, o);   // 128MB: evict-first
        }
    }
}

// =====================================================================
// GEMM: CTA = 128(M) x 256(N); two independent 128-thread groups, each a
// 128x128 N-half with its own 3-stage cp.async ring + named barrier.
// Per group: 4 warps (2M x 2N), warp tile 64x64, mma.sync.m16n8k16.
// kt loop manually unrolled x3 (compile-time stage addresses).
// NOTE: swizzle applied AFTER adding colb (SWZ128 is not linear!).
// =====================================================================
#define G_TK 64
#define G_KTILES (K_DIM / G_TK)      // 64
#define GA_BYTES (128 * G_TK * 2)    // 16384
#define GB_BYTES (128 * G_TK * 2)    // 16384
#define G_STAGE (GA_BYTES + GB_BYTES)          // 32768
#define G_SMEM_PER (3 * G_STAGE)               // 98304
#define H_SMEM (2 * G_SMEM_PER)                // 196608

__global__ void __launch_bounds__(256, 1)
gemm_hmma(const float* __restrict__ scale, const float* __restrict__ bias,
          float* __restrict__ out) {
    extern __shared__ __align__(1024) char smem[];
    const int tid = threadIdx.x;
    const int lane = tid & 31;
    const int wid = tid >> 5;
    const int g = wid >> 2;            // group 0 / 1
    const int wg = wid & 3;
    const int wm = wg & 1;
    const int wn = wg >> 1;
    const int tg = tid & 127;
    const uint32_t sg = smem_u32(smem) + g * G_SMEM_PER;

    // tile rasterization: 8 consecutive CTAs share one tn
    const int nTN = N_DIM / 256;       // 64
    const int GROUPM = 8;
    const int npg = GROUPM * nTN;
    int pid = blockIdx.x;
    int grp = pid / npg;
    int inp = pid - grp * npg;
    int tm = grp * GROUPM + (inp % GROUPM);
    int tn = inp / GROUPM;

    const char* gA = (const char*)(g_A + (size_t)tm * 128 * K_DIM);
    const char* gB = (const char*)(g_B + ((size_t)tn * 256 + g * 128) * K_DIM);

    const int ld_row = tg >> 3;                 // 0..15 (+16 per i)
    const int ld_col = (tg & 7) * 16;

    auto load_A = [&](uint32_t sa, int kt) {
        size_t kofs = (size_t)kt * 128;
#pragma unroll
        for (int i = 0; i < 8; i++) {
            int row = ld_row + 16 * i;
            CP_ASYNC16(sa + SWZ128(row * 128 + ld_col),
                       gA + (size_t)row * (K_DIM * 2) + kofs + ld_col);
        }
    };
    auto load_B = [&](uint32_t sB, int kt) {
        size_t kofs = (size_t)kt * 128;
#pragma unroll
        for (int i = 0; i < 8; i++) {
            int row = ld_row + 16 * i;
            CP_ASYNC16(sB + SWZ128(row * 128 + ld_col),
                       gB + (size_t)row * (K_DIM * 2) + kofs + ld_col);
        }
    };

    float acc[4][8][4];
#pragma unroll
    for (int i = 0; i < 4; i++)
#pragma unroll
        for (int j = 0; j < 8; j++)
#pragma unroll
            for (int k = 0; k < 4; k++) acc[i][j][k] = 0.f;

    const int a_row = lane & 15;
    const int a_col = (lane >> 4) * 16;
    const int b_row = (lane & 7) + ((lane >> 4) << 3);
    const int b_col = ((lane >> 3) & 1) * 16;

    // UN-swizzled per-fragment bases; swizzle happens after adding colb
    uint32_t a_base[4], b_base[4];
#pragma unroll
    for (int mt = 0; mt < 4; mt++)
        a_base[mt] = (wm * 64 + mt * 16 + a_row) * 128 + a_col;
#pragma unroll
    for (int nt2 = 0; nt2 < 4; nt2++)
        b_base[nt2] = (wn * 64 + nt2 * 16 + b_row) * 128 + b_col;

    auto do_ks = [&](uint32_t sa, uint32_t sB, int ks) {
        const uint32_t colb = ks * 32;
        uint32_t afr[4][4], bfr[4][4];
        LDMX4(afr[0][0], afr[0][1], afr[0][2], afr[0][3],
              sa + SWZ128(a_base[0] + colb));
#pragma unroll
        for (int nt2 = 0; nt2 < 4; nt2++)
            LDMX4(bfr[nt2][0], bfr[nt2][1], bfr[nt2][2], bfr[nt2][3],
                  sB + SWZ128(b_base[nt2] + colb));
#pragma unroll
        for (int mt = 1; mt < 4; mt++)
            LDMX4(afr[mt][0], afr[mt][1], afr[mt][2], afr[mt][3],
                  sa + SWZ128(a_base[mt] + colb));
#pragma unroll
        for (int mt = 0; mt < 4; mt++) {
#pragma unroll
            for (int nt = 0; nt < 8; nt++) {
                uint32_t b0 = (nt & 1) ? bfr[nt >> 1][2] : bfr[nt >> 1][0];
                uint32_t b1 = (nt & 1) ? bfr[nt >> 1][3] : bfr[nt >> 1][1];
                asm volatile(
                    "mma.sync.aligned.m16n8k16.row.col.f32.f16.f16.f32 "
                    "{%0,%1,%2,%3}, {%4,%5,%6,%7}, {%8,%9}, {%0,%1,%2,%3};"
                    : "+f"(acc[mt][nt][0]), "+f"(acc[mt][nt][1]),
                      "+f"(acc[mt][nt][2]), "+f"(acc[mt][nt][3])
                    : "r"(afr[mt][0]), "r"(afr[mt][1]),
                      "r"(afr[mt][2]), "r"(afr[mt][3]),
                      "r"(b0), "r"(b1));
            }
        }
    };

    const uint32_t st0 = sg, st1 = sg + G_STAGE, st2 = sg + 2 * G_STAGE;

    // prologue: fill stages 0 and 1
    load_A(st0, 0); load_B(st0 + GA_BYTES, 0); CP_COMMIT();
    load_A(st1, 1); load_B(st1 + GA_BYTES, 1); CP_COMMIT();

    auto iter = [&](int kt, uint32_t cur, uint32_t pre) {
        if (kt + 1 >= G_KTILES) { CP_WAIT(0); }
        else                    { CP_WAIT(1); }
        GROUP_BAR(1 + g);
        const uint32_t sa = cur, sB = cur + GA_BYTES;
        const bool pf = (kt + 2 < G_KTILES);
        do_ks(sa, sB, 0);
        if (pf) load_A(pre, kt + 2);
        do_ks(sa, sB, 1);
        if (pf) { load_B(pre + GA_BYTES, kt + 2); CP_COMMIT(); }
        do_ks(sa, sB, 2);
        do_ks(sa, sB, 3);
    };

    // main: kt 0..62 in triples, tail kt=63 (63 % 3 == 0 -> stage st0)
#pragma unroll 1
    for (int kt0 = 0; kt0 < 63; kt0 += 3) {
        iter(kt0 + 0, st0, st2);
        iter(kt0 + 1, st1, st0);
        iter(kt0 + 2, st2, st1);
    }
    iter(63, st0, st2);

    // ---- epilogue: fuse per-channel scale + bias, streaming stores ----
    const int ncol0 = tn * 256 + g * 128 + wn * 64;
    float2 sc2[8], bi2[8];
#pragma unroll
    for (int nt = 0; nt < 8; nt++) {
        int cn = ncol0 + nt * 8 + 2 * (lane & 3);
        sc2[nt] = *(const float2*)(scale + cn);
        bi2[nt] = *(const float2*)(bias + cn);
    }
#pragma unroll
    for (int mt = 0; mt < 4; mt++) {
        int r0 = tm * 128 + wm * 64 + mt * 16 + (lane >> 2);
        int r1 = r0 + 8;
#pragma unroll
        for (int nt = 0; nt < 8; nt++) {
            int cn = ncol0 + nt * 8 + 2 * (lane & 3);
            float2 o0, o1;
            o0.x = acc[mt][nt][0] * sc2[nt].x + bi2[nt].x;
            o0.y = acc[mt][nt][1] * sc2[nt].y + bi2[nt].y;
            o1.x = acc[mt][nt][2] * sc2[nt].x + bi2[nt].x;
            o1.y = acc[mt][nt][3] * sc2[nt].y + bi2[nt].y;
            stcs8(out + (size_t)r0 * N_DIM + cn, o0);
            stcs8(out + (size_t)r1 * N_DIM + cn, o1);
        }
    }
}

// ---------------- launch ----------------
extern "C" void kernel_launch(void* const* d_in, const int* in_sizes, int n_in,
                              void* d_out, int out_size) {
    const float* x     = (const float*)d_in[0];
    const int*   w     = (const int*)d_in[1];   // int8 values shipped as int32
    const float* scale = (const float*)d_in[2];
    const float* bias  = (const float*)d_in[3];
    float*       out   = (float*)d_out;

    cudaFuncSetAttribute(gemm_hmma,
                         cudaFuncAttributeMaxDynamicSharedMemorySize, H_SMEM);

    cvt_kernel<<<XB + WB, 256>>>(x, w);
    gemm_hmma<<<(M_DIM / 128) * (N_DIM / 256), 256, H_SMEM>>>(scale, bias, out);
}